// round 17
// baseline (speedup 1.0000x reference)
#include <cuda_runtime.h>
#include <cuda_bf16.h>
#include <cuda_fp16.h>
#include <cstdint>
#include <math.h>

// Problem constants
#define BSZ   2
#define NQ    2048
#define NK    2048
#define DM    1024
#define AM    1024
#define NH    16
#define DHD   64
#define TOKQ  (BSZ*NQ)   // 4096
#define TOKK  (BSZ*NK)   // 4096
#define SIG_SCALE 0.35355339059327373f
#define EPSF  1e-5f

// ---------------------------------------------------------------------------
// Scratch
// ---------------------------------------------------------------------------
__device__ __half g_xqh [TOKQ * DM];
__device__ __half g_kfh [TOKK * DM];
__device__ __half g_Wqh [AM * DM];
__device__ __half g_Wkh [AM * DM];
__device__ __half g_Wvh [AM * DM];
__device__ __half g_Woh [DM * AM];
__device__ __half g_qh  [TOKQ * AM];
__device__ __half g_kh  [TOKK * AM];
__device__ __half g_vh  [TOKK * AM];
__device__ __half g_ctxh[TOKQ * AM];
__device__ __half g_oh0 [TOKQ * DM];   // wo partial (K 0..511)
__device__ __half g_oh1 [TOKQ * DM];   // wo partial (K 512..1023)

// ---------------------------------------------------------------------------
// Low-level helpers
// ---------------------------------------------------------------------------
__device__ __forceinline__ uint32_t smem_u32(const void* p) {
    uint32_t a;
    asm("{ .reg .u64 t; cvta.to.shared.u64 t, %1; cvt.u32.u64 %0, t; }"
        : "=r"(a) : "l"(p));
    return a;
}
__device__ __forceinline__ void cp_async16(uint32_t saddr, const void* gaddr) {
    asm volatile("cp.async.cg.shared.global [%0], [%1], 16;"
                 :: "r"(saddr), "l"(gaddr));
}
#define CP_COMMIT() asm volatile("cp.async.commit_group;" ::: "memory")
#define CP_WAIT(N)  asm volatile("cp.async.wait_group %0;" :: "n"(N) : "memory")

__device__ __forceinline__ void ldsm4(uint32_t& r0, uint32_t& r1,
                                      uint32_t& r2, uint32_t& r3, uint32_t a) {
    asm volatile("ldmatrix.sync.aligned.m8n8.x4.shared.b16 {%0,%1,%2,%3}, [%4];"
                 : "=r"(r0), "=r"(r1), "=r"(r2), "=r"(r3) : "r"(a));
}
__device__ __forceinline__ void ldsm4t(uint32_t& r0, uint32_t& r1,
                                       uint32_t& r2, uint32_t& r3, uint32_t a) {
    asm volatile("ldmatrix.sync.aligned.m8n8.x4.trans.shared.b16 {%0,%1,%2,%3}, [%4];"
                 : "=r"(r0), "=r"(r1), "=r"(r2), "=r"(r3) : "r"(a));
}
__device__ __forceinline__ void mma_h16(uint32_t* c, const uint32_t* a,
                                        uint32_t b0, uint32_t b1) {
    asm volatile(
        "mma.sync.aligned.m16n8k16.row.col.f16.f16.f16.f16 "
        "{%0,%1}, {%2,%3,%4,%5}, {%6,%7}, {%0,%1};"
        : "+r"(c[0]), "+r"(c[1])
        : "r"(a[0]), "r"(a[1]), "r"(a[2]), "r"(a[3]), "r"(b0), "r"(b1));
}

__device__ __forceinline__ uint32_t sig16x2(uint32_t s) {
    uint32_t u, t, r;
    asm("fma.rn.f16x2 %0, %1, %2, %3;"
        : "=r"(u) : "r"(s), "r"(0x38003800u), "r"(0xBE00BE00u)); // *0.5 - 1.5
    asm("tanh.approx.f16x2 %0, %1;" : "=r"(t) : "r"(u));
    asm("fma.rn.f16x2 %0, %1, %2, %2;" : "=r"(r) : "r"(t), "r"(0x38003800u));
    return r;
}
__device__ __forceinline__ float2 h2f(uint32_t u) {
    __half2 h = *reinterpret_cast<__half2*>(&u);
    return __half22float2(h);
}
__device__ __forceinline__ void store2(__half* p, float a, float b) {
    uint32_t r;
    asm("cvt.rn.f16x2.f32 %0, %1, %2;" : "=r"(r) : "f"(b), "f"(a));
    *(uint32_t*)p = r;
}

// ---------------------------------------------------------------------------
// GEMM mainloop: CTA 128x128, warp tile 32x64 (8 warps 4m x 2n), f16 accum,
// K stage 64, double-buffered cp.async (64 KB smem). kstages = K-extent/64.
// ---------------------------------------------------------------------------
#define GSM_STAGE 32768             // A 16KB + B 16KB
#define GSM_TOTAL (2 * GSM_STAGE)   // 64 KB

__device__ __forceinline__ void gemm_stage_load(
    uint32_t st, const __half* Ag, const __half* Bg, int K, int kt, int tid) {
    uint32_t sa = st, sb = st + 16384;
    #pragma unroll
    for (int s = 0; s < 4; s++) {
        int i = tid + s * 256;
        int row = i >> 3, cc = i & 7;
        uint32_t sw = (uint32_t)((cc ^ (row & 7)) << 4);
        cp_async16(sa + row * 128 + sw, Ag + (size_t)row * K + kt * 64 + cc * 8);
        cp_async16(sb + row * 128 + sw, Bg + (size_t)row * K + kt * 64 + cc * 8);
    }
}

__device__ __forceinline__ void gemm_mainloop(
    const __half* __restrict__ Ag, const __half* __restrict__ Bg,
    int K, int kstages, char* gsm, uint32_t acc[2][8][2]) {
    uint32_t st[2] = { smem_u32(gsm), smem_u32(gsm) + GSM_STAGE };
    int tid = threadIdx.x, w = tid >> 5, lane = tid & 31;
    int wm = (w >> 1) * 32, wn = (w & 1) * 64;

    #pragma unroll
    for (int i = 0; i < 2; i++)
        #pragma unroll
        for (int j = 0; j < 8; j++) { acc[i][j][0] = 0u; acc[i][j][1] = 0u; }

    gemm_stage_load(st[0], Ag, Bg, K, 0, tid);
    CP_COMMIT();

    for (int kt = 0; kt < kstages; kt++) {
        if (kt + 1 < kstages) {
            gemm_stage_load(st[(kt + 1) & 1], Ag, Bg, K, kt + 1, tid);
            CP_COMMIT();
            CP_WAIT(1);
        } else {
            CP_WAIT(0);
        }
        __syncthreads();

        uint32_t ab = st[kt & 1], bb = ab + 16384;
        #pragma unroll
        for (int ks = 0; ks < 4; ks++) {
            uint32_t af[2][4];
            #pragma unroll
            for (int mi = 0; mi < 2; mi++) {
                int row = wm + mi * 16 + (lane & 15);
                int cc  = ks * 2 + (lane >> 4);
                ldsm4(af[mi][0], af[mi][1], af[mi][2], af[mi][3],
                      ab + row * 128 + ((cc ^ (row & 7)) << 4));
            }
            #pragma unroll
            for (int n16 = 0; n16 < 4; n16++) {
                int row = wn + n16 * 16 + (lane & 7) + ((lane >> 4) << 3);
                int cc  = ks * 2 + ((lane >> 3) & 1);
                uint32_t b0, b1, b2, b3;
                ldsm4(b0, b1, b2, b3, bb + row * 128 + ((cc ^ (row & 7)) << 4));
                #pragma unroll
                for (int mi = 0; mi < 2; mi++) {
                    mma_h16(acc[mi][n16 * 2 + 0], af[mi], b0, b1);
                    mma_h16(acc[mi][n16 * 2 + 1], af[mi], b2, b3);
                }
            }
        }
        __syncthreads();
    }
}

// ---------------------------------------------------------------------------
// QKV projection with FUSED qk-norm (warp's 64 cols == one full head).
// blockIdx.z: 0=Q (qknorm), 1=K (kknorm), 2=V (plain).
// ---------------------------------------------------------------------------
__global__ __launch_bounds__(256, 3)
void qkv_gemm_kernel(const __half* __restrict__ xq,
                     const __half* __restrict__ kf,
                     const __half* __restrict__ Wq,
                     const __half* __restrict__ Wk,
                     const __half* __restrict__ Wv,
                     const float* __restrict__ qn_s,
                     const float* __restrict__ qn_b,
                     const float* __restrict__ kn_s,
                     const float* __restrict__ kn_b,
                     __half* __restrict__ qo,
                     __half* __restrict__ ko,
                     __half* __restrict__ vo) {
    extern __shared__ __align__(1024) char gsm[];
    int z = blockIdx.z;
    const __half* A = (z == 0) ? xq : kf;
    const __half* B = (z == 0) ? Wq : (z == 1) ? Wk : Wv;
    __half* C = (z == 0) ? qo : (z == 1) ? ko : vo;
    const float* sc = (z == 0) ? qn_s : kn_s;
    const float* bi = (z == 0) ? qn_b : kn_b;

    uint32_t acc[2][8][2];
    gemm_mainloop(A + (size_t)(blockIdx.y * 128) * DM,
                  B + (size_t)(blockIdx.x * 128) * DM,
                  DM, DM / 64, gsm, acc);

    int tid = threadIdx.x, w = tid >> 5, lane = tid & 31;
    int wm = (w >> 1) * 32, wn = (w & 1) * 64;
    int crow0 = blockIdx.y * 128 + wm + (lane >> 2);
    int ccol0 = blockIdx.x * 128 + wn + (lane & 3) * 2;

    if (z == 2) {
        #pragma unroll
        for (int mi = 0; mi < 2; mi++) {
            #pragma unroll
            for (int nj = 0; nj < 8; nj++) {
                int row = crow0 + mi * 16;
                int col = ccol0 + nj * 8;
                *(uint32_t*)(C + (size_t)row * AM + col)       = acc[mi][nj][0];
                *(uint32_t*)(C + (size_t)(row + 8) * AM + col) = acc[mi][nj][1];
            }
        }
        return;
    }

    // ---- fused qk-norm: warp's 64 cols = one full head; quad shuffle ----
    #pragma unroll
    for (int mi = 0; mi < 2; mi++) {
        float slo = 0.f, qlo = 0.f, shi = 0.f, qhi = 0.f;
        #pragma unroll
        for (int nj = 0; nj < 8; nj++) {
            float2 p0 = h2f(acc[mi][nj][0]);
            float2 p1 = h2f(acc[mi][nj][1]);
            slo += p0.x + p0.y; qlo += p0.x * p0.x + p0.y * p0.y;
            shi += p1.x + p1.y; qhi += p1.x * p1.x + p1.y * p1.y;
        }
        #pragma unroll
        for (int o = 1; o <= 2; o <<= 1) {
            slo += __shfl_xor_sync(0xffffffffu, slo, o);
            qlo += __shfl_xor_sync(0xffffffffu, qlo, o);
            shi += __shfl_xor_sync(0xffffffffu, shi, o);
            qhi += __shfl_xor_sync(0xffffffffu, qhi, o);
        }
        float m0 = slo * (1.f / DHD);
        float m1 = shi * (1.f / DHD);
        float r0 = rsqrtf(qlo * (1.f / DHD) - m0 * m0 + EPSF);
        float r1 = rsqrtf(qhi * (1.f / DHD) - m1 * m1 + EPSF);

        int row0 = crow0 + mi * 16;
        #pragma unroll
        for (int nj = 0; nj < 8; nj++) {
            int cih = nj * 8 + (lane & 3) * 2;
            float sc0 = sc[cih], sc1 = sc[cih + 1];
            float bi0 = bi[cih], bi1 = bi[cih + 1];
            int col = ccol0 + nj * 8;
            float2 p0 = h2f(acc[mi][nj][0]);
            float2 p1 = h2f(acc[mi][nj][1]);
            float a0 = ((p0.x - m0) * r0 * sc0 + bi0) * SIG_SCALE;
            float a1 = ((p0.y - m0) * r0 * sc1 + bi1) * SIG_SCALE;
            float a2 = ((p1.x - m1) * r1 * sc0 + bi0) * SIG_SCALE;
            float a3 = ((p1.y - m1) * r1 * sc1 + bi1) * SIG_SCALE;
            store2(C + (size_t)row0 * AM + col, a0, a1);
            store2(C + (size_t)(row0 + 8) * AM + col, a2, a3);
        }
    }
}

// Wo projection, split-K=2: blockIdx.z = K half; partial f16 outputs.
__global__ __launch_bounds__(256, 3)
void wo_gemm_kernel(const __half* __restrict__ A,
                    const __half* __restrict__ B,
                    __half* __restrict__ C0,
                    __half* __restrict__ C1) {
    extern __shared__ __align__(1024) char gsm[];
    int z = blockIdx.z;
    __half* C = z ? C1 : C0;
    uint32_t acc[2][8][2];
    gemm_mainloop(A + (size_t)(blockIdx.y * 128) * AM + z * 512,
                  B + (size_t)(blockIdx.x * 128) * AM + z * 512,
                  AM, 512 / 64, gsm, acc);
    int tid = threadIdx.x, w = tid >> 5, lane = tid & 31;
    int wm = (w >> 1) * 32, wn = (w & 1) * 64;
    int crow0 = blockIdx.y * 128 + wm + (lane >> 2);
    int ccol0 = blockIdx.x * 128 + wn + (lane & 3) * 2;
    #pragma unroll
    for (int mi = 0; mi < 2; mi++) {
        #pragma unroll
        for (int nj = 0; nj < 8; nj++) {
            int row = crow0 + mi * 16, col = ccol0 + nj * 8;
            *(uint32_t*)(C + (size_t)row * DM + col)       = acc[mi][nj][0];
            *(uint32_t*)(C + (size_t)(row + 8) * DM + col) = acc[mi][nj][1];
        }
    }
}

// ---------------------------------------------------------------------------
// Fused sigmoid attention: q-tile 128, 8 warps each 16 q-rows x 64 keys;
// Q smem-staged; 128-key stages double-buffered (80 KB smem), occ 2.
// Inner loop PIPELINED in 16-key slices: QK(i+1) independent of sig/PV(i).
// ---------------------------------------------------------------------------
#define ASM_Q    0
#define ASM_K(s) (16384 + (s) * 32768)
#define ASM_V(s) (16384 + (s) * 32768 + 16384)
#define ASM_TOTAL (16384 + 2 * 32768)          // 80 KB

__global__ __launch_bounds__(256, 2)
void attn_mma_kernel(const __half* __restrict__ Q,
                     const __half* __restrict__ Km,
                     const __half* __restrict__ V,
                     __half* __restrict__ O) {
    extern __shared__ __align__(1024) char asm_[];
    uint32_t sb = smem_u32(asm_);
    int tid = threadIdx.x, w = tid >> 5, lane = tid & 31;
    int q0 = blockIdx.x * 128, h = blockIdx.y, b = blockIdx.z;

    const __half* Qg = Q  + ((size_t)(b * NQ + q0)) * AM + h * DHD;
    const __half* Kg = Km + ((size_t)(b * NK)) * AM + h * DHD;
    const __half* Vg = V  + ((size_t)(b * NK)) * AM + h * DHD;

    #pragma unroll
    for (int s = 0; s < 4; s++) {
        int i = tid + s * 256;
        int row = i >> 3, cc = i & 7;
        cp_async16(sb + ASM_Q + row * 128 + ((cc ^ (row & 7)) << 4),
                   Qg + (size_t)row * AM + cc * 8);
    }
    #pragma unroll
    for (int s = 0; s < 4; s++) {
        int i = tid + s * 256;
        int row = i >> 3, cc = i & 7;
        uint32_t sw = (uint32_t)((cc ^ (row & 7)) << 4);
        cp_async16(sb + ASM_K(0) + row * 128 + sw, Kg + (size_t)row * AM + cc * 8);
        cp_async16(sb + ASM_V(0) + row * 128 + sw, Vg + (size_t)row * AM + cc * 8);
    }
    CP_COMMIT();

    uint32_t qf[4][4];
    uint32_t cacc[8][2];
    #pragma unroll
    for (int j = 0; j < 8; j++) { cacc[j][0] = 0u; cacc[j][1] = 0u; }

    const int NT = NK / 128;   // 16 stages
    for (int kt = 0; kt < NT; kt++) {
        int buf = kt & 1;
        if (kt + 1 < NT) {
            int nb = (kt + 1) & 1;
            const __half* Kg2 = Kg + (size_t)(kt + 1) * 128 * AM;
            const __half* Vg2 = Vg + (size_t)(kt + 1) * 128 * AM;
            #pragma unroll
            for (int s = 0; s < 4; s++) {
                int i = tid + s * 256;
                int row = i >> 3, cc = i & 7;
                uint32_t sw = (uint32_t)((cc ^ (row & 7)) << 4);
                cp_async16(sb + ASM_K(nb) + row * 128 + sw, Kg2 + (size_t)row * AM + cc * 8);
                cp_async16(sb + ASM_V(nb) + row * 128 + sw, Vg2 + (size_t)row * AM + cc * 8);
            }
            CP_COMMIT();
            CP_WAIT(1);
        } else {
            CP_WAIT(0);
        }
        __syncthreads();

        if (kt == 0) {
            #pragma unroll
            for (int ks = 0; ks < 4; ks++) {
                int row = w * 16 + (lane & 15);
                int cc  = ks * 2 + (lane >> 4);
                ldsm4(qf[ks][0], qf[ks][1], qf[ks][2], qf[ks][3],
                      sb + ASM_Q + row * 128 + ((cc ^ (row & 7)) << 4));
            }
        }

        uint32_t kb = sb + ASM_K(buf);
        uint32_t vb = sb + ASM_V(buf);

        // 8 pipelined 16-key slices across the 128-key stage.
        // Per slice: QK (4 ldsm + 8 mma) -> sigmoid (4 f16x2 chains)
        // -> PV (4 ldsmt + 8 mma). Slices are independent -> ILP overlap.
        #pragma unroll
        for (int sl = 0; sl < 8; sl++) {
            // ---- QK for 16 keys (rows sl*16 .. sl*16+15) ----
            uint32_t sacc[2][2];
            sacc[0][0] = 0u; sacc[0][1] = 0u;
            sacc[1][0] = 0u; sacc[1][1] = 0u;
            #pragma unroll
            for (int ks = 0; ks < 4; ks++) {
                int row = sl * 16 + (lane & 7) + ((lane >> 4) << 3);
                int cc  = ks * 2 + ((lane >> 3) & 1);
                uint32_t b0, b1, b2, b3;
                ldsm4(b0, b1, b2, b3, kb + row * 128 + ((cc ^ (row & 7)) << 4));
                mma_h16(sacc[0], qf[ks], b0, b1);
                mma_h16(sacc[1], qf[ks], b2, b3);
            }

            // ---- sigmoid in place -> P A-fragment (one k16 block) ----
            uint32_t pa[4];
            pa[0] = sig16x2(sacc[0][0]);
            pa[1] = sig16x2(sacc[0][1]);
            pa[2] = sig16x2(sacc[1][0]);
            pa[3] = sig16x2(sacc[1][1]);

            // ---- ctx += P @ V over these 16 keys ----
            #pragma unroll
            for (int djj = 0; djj < 4; djj++) {
                int row = sl * 16 + (lane & 15);
                int cc  = djj * 2 + (lane >> 4);
                uint32_t v0, v1, v2, v3;
                ldsm4t(v0, v1, v2, v3, vb + row * 128 + ((cc ^ (row & 7)) << 4));
                mma_h16(cacc[djj * 2 + 0], pa, v0, v1);
                mma_h16(cacc[djj * 2 + 1], pa, v2, v3);
            }
        }
        __syncthreads();
    }

    __half* Ob = O + ((size_t)(b * NQ)) * AM + h * DHD;
    int r0 = q0 + w * 16 + (lane >> 2);
    #pragma unroll
    for (int j = 0; j < 8; j++) {
        int col = j * 8 + (lane & 3) * 2;
        *(uint32_t*)(Ob + (size_t)r0 * AM + col)       = cacc[j][0];
        *(uint32_t*)(Ob + (size_t)(r0 + 8) * AM + col) = cacc[j][1];
    }
}

// ---------------------------------------------------------------------------
// Fused prep: LN(query)->f16, cvt(kf)->f16, cvt(4 weights)->f16 in one launch.
// ---------------------------------------------------------------------------
__device__ __forceinline__ float warp_sum(float v) {
    #pragma unroll
    for (int o = 16; o; o >>= 1) v += __shfl_xor_sync(0xffffffffu, v, o);
    return v;
}

__global__ void prep_kernel(const float* __restrict__ qf,
                            const float* __restrict__ kf,
                            const float* __restrict__ Wq,
                            const float* __restrict__ Wk,
                            const float* __restrict__ Wv,
                            const float* __restrict__ Wo,
                            const float* __restrict__ lq_s,
                            const float* __restrict__ lq_b,
                            __half* __restrict__ xqh,
                            __half* __restrict__ kfh,
                            __half* __restrict__ Wqh,
                            __half* __restrict__ Wkh,
                            __half* __restrict__ Wvh,
                            __half* __restrict__ Woh) {
    int bidx = blockIdx.x;
    if (bidx >= TOKQ) {
        const float* src;
        __half* dst;
        int j = bidx - TOKQ;
        if (j < 4096) {
            size_t off = (size_t)j * 1024;
            src = kf + off; dst = kfh + off;
        } else {
            j -= 4096;
            int wsel = j >> 10;
            size_t off = (size_t)(j & 1023) * 1024;
            if      (wsel == 0) { src = Wq + off; dst = Wqh + off; }
            else if (wsel == 1) { src = Wk + off; dst = Wkh + off; }
            else if (wsel == 2) { src = Wv + off; dst = Wvh + off; }
            else                { src = Wo + off; dst = Woh + off; }
        }
        int i = threadIdx.x * 4;
        float4 v = *(const float4*)(src + i);
        store2(dst + i,     v.x, v.y);
        store2(dst + i + 2, v.z, v.w);
        return;
    }

    int row = bidx;
    const float* xr = qf + (size_t)row * DM;
    __half* yr = xqh + (size_t)row * DM;
    __shared__ float buf[DM];
    __shared__ float red[16];
    float s = 0.f, s2 = 0.f;
    for (int i = threadIdx.x; i < DM; i += 256) {
        float v = xr[i];
        buf[i] = v;
        s += v; s2 += v * v;
    }
    s = warp_sum(s); s2 = warp_sum(s2);
    int w = threadIdx.x >> 5, l = threadIdx.x & 31;
    if (l == 0) { red[w] = s; red[8 + w] = s2; }
    __syncthreads();
    if (threadIdx.x < 32) {
        float a  = (l < 8) ? red[l] : 0.f;
        float b2 = (l < 8) ? red[8 + l] : 0.f;
        a = warp_sum(a); b2 = warp_sum(b2);
        if (l == 0) { red[0] = a; red[1] = b2; }
    }
    __syncthreads();
    float mean = red[0] * (1.f / DM);
    float var  = red[1] * (1.f / DM) - mean * mean;
    float rs = rsqrtf(var + EPSF);
    for (int i = threadIdx.x; i < DM; i += 256)
        yr[i] = __float2half((buf[i] - mean) * rs * lq_s[i] + lq_b[i]);
}

// Final: t = resid + gamma*(oh0+oh1), LayerNorm -> out
__global__ void final_ln_kernel(const float* __restrict__ resid,
                                const __half* __restrict__ o0,
                                const __half* __restrict__ o1,
                                const float* __restrict__ gamma,
                                const float* __restrict__ sc,
                                const float* __restrict__ bi,
                                float* __restrict__ out) {
    int row = blockIdx.x;
    const float* rr = resid + (size_t)row * DM;
    const __half* p0 = o0 + (size_t)row * DM;
    const __half* p1 = o1 + (size_t)row * DM;
    float* yr = out + (size_t)row * DM;
    __shared__ float buf[DM];
    __shared__ float red[16];
    float s = 0.f, s2 = 0.f;
    for (int i = threadIdx.x; i < DM; i += 256) {
        float ov = __half2float(p0[i]) + __half2float(p1[i]);
        float t = rr[i] + gamma[i] * ov;
        buf[i] = t;
        s += t; s2 += t * t;
    }
    s = warp_sum(s); s2 = warp_sum(s2);
    int w = threadIdx.x >> 5, l = threadIdx.x & 31;
    if (l == 0) { red[w] = s; red[8 + w] = s2; }
    __syncthreads();
    if (threadIdx.x < 32) {
        float a  = (l < 8) ? red[l] : 0.f;
        float b2 = (l < 8) ? red[8 + l] : 0.f;
        a = warp_sum(a); b2 = warp_sum(b2);
        if (l == 0) { red[0] = a; red[1] = b2; }
    }
    __syncthreads();
    float mean = red[0] * (1.f / DM);
    float var  = red[1] * (1.f / DM) - mean * mean;
    float rs = rsqrtf(var + EPSF);
    for (int i = threadIdx.x; i < DM; i += 256)
        yr[i] = (buf[i] - mean) * rs * sc[i] + bi[i];
}

// ---------------------------------------------------------------------------
// Launch
// ---------------------------------------------------------------------------
extern "C" void kernel_launch(void* const* d_in, const int* in_sizes, int n_in,
                              void* d_out, int out_size) {
    (void)in_sizes; (void)n_in; (void)out_size;
    const float* qf    = (const float*)d_in[0];
    const float* kf    = (const float*)d_in[1];
    const float* Wq    = (const float*)d_in[2];
    const float* Wk    = (const float*)d_in[3];
    const float* Wv    = (const float*)d_in[4];
    const float* Wo    = (const float*)d_in[5];
    const float* qn_s  = (const float*)d_in[6];
    const float* qn_b  = (const float*)d_in[7];
    const float* kn_s  = (const float*)d_in[8];
    const float* kn_b  = (const float*)d_in[9];
    const float* lq_s  = (const float*)d_in[10];
    const float* lq_b  = (const float*)d_in[11];
    const float* lo_s  = (const float*)d_in[12];
    const float* lo_b  = (const float*)d_in[13];
    const float* gamma = (const float*)d_in[14];
    float* out = (float*)d_out;

    __half *xqh, *kfh, *Wqh, *Wkh, *Wvh, *Woh, *qh, *kh, *vh, *ctxh, *oh0, *oh1;
    cudaGetSymbolAddress((void**)&xqh,  g_xqh);
    cudaGetSymbolAddress((void**)&kfh,  g_kfh);
    cudaGetSymbolAddress((void**)&Wqh,  g_Wqh);
    cudaGetSymbolAddress((void**)&Wkh,  g_Wkh);
    cudaGetSymbolAddress((void**)&Wvh,  g_Wvh);
    cudaGetSymbolAddress((void**)&Woh,  g_Woh);
    cudaGetSymbolAddress((void**)&qh,   g_qh);
    cudaGetSymbolAddress((void**)&kh,   g_kh);
    cudaGetSymbolAddress((void**)&vh,   g_vh);
    cudaGetSymbolAddress((void**)&ctxh, g_ctxh);
    cudaGetSymbolAddress((void**)&oh0,  g_oh0);
    cudaGetSymbolAddress((void**)&oh1,  g_oh1);

    cudaFuncSetAttribute(qkv_gemm_kernel,
                         cudaFuncAttributeMaxDynamicSharedMemorySize, GSM_TOTAL);
    cudaFuncSetAttribute(wo_gemm_kernel,
                         cudaFuncAttributeMaxDynamicSharedMemorySize, GSM_TOTAL);
    cudaFuncSetAttribute(attn_mma_kernel,
                         cudaFuncAttributeMaxDynamicSharedMemorySize, ASM_TOTAL);

    // 1) fused prep
    prep_kernel<<<TOKQ + 4096 + 4096, 256>>>(
        qf, kf, Wq, Wk, Wv, Wo, lq_s, lq_b,
        xqh, kfh, Wqh, Wkh, Wvh, Woh);
    // 2) merged Q/K/V projections with fused qk-norm
    qkv_gemm_kernel<<<dim3(AM / 128, TOKQ / 128, 3), 256, GSM_TOTAL>>>(
        xqh, kfh, Wqh, Wkh, Wvh, qn_s, qn_b, kn_s, kn_b, qh, kh, vh);
    // 3) fused sigmoid attention (16-key pipelined slices)
    dim3 agrid(NQ / 128, NH, BSZ);
    attn_mma_kernel<<<agrid, 256, ASM_TOTAL>>>(qh, kh, vh, ctxh);
    // 4) output projection, split-K=2 -> two f16 partials
    wo_gemm_kernel<<<dim3(DM / 128, TOKQ / 128, 2), 256, GSM_TOTAL>>>(
        ctxh, Woh, oh0, oh1);
    // 5) residual + gamma*(oh0+oh1) + post-LN
    final_ln_kernel<<<TOKQ, 256>>>(qf, oh0, oh1, gamma, lo_s, lo_b, out);
}